// round 14
// baseline (speedup 1.0000x reference)
#include <cuda_runtime.h>
#include <cuda_fp16.h>

#define BB 2
#define SS 4096
#define DD 128
#define HH 4
#define DH 32
#define BHT (BB*HH)
#define KS 4
#define QSCALE 0.17677669529663687f   // 1/sqrt(32)
#define LOG2E  1.4426950408889634f

typedef unsigned int u32;

// ---------------- scratch (device globals; no allocations) ----------------
__device__ __align__(16) __half g_qh[(size_t)BHT*SS*DH];
__device__ __align__(16) __half g_kh[(size_t)BHT*SS*DH];
__device__ __align__(16) __half g_vh[(size_t)BHT*SS*DH];
__device__ __align__(16) __half g_xh[(size_t)BB*SS*DD];
__device__ __align__(16) __half g_wh[3*128*128];
__device__ __align__(16) float g_xpart[BB*32][DD];
__device__ __align__(16) float g_vsum[BHT*DH];
__device__ __align__(16) float g_lpart[(size_t)BHT*SS*KS];
__device__ __align__(16) __half g_oparth[(size_t)BHT*SS*KS*DH];

// ---------------- asm helpers ----------------
__device__ __forceinline__ u32 smaddr(const void* p) {
    u32 a;
    asm("{.reg .u64 t; cvta.to.shared.u64 t, %1; cvt.u32.u64 %0, t;}" : "=r"(a) : "l"(p));
    return a;
}
#define LDSM4(r0,r1,r2,r3,a) \
    asm volatile("ldmatrix.sync.aligned.m8n8.x4.shared.b16 {%0,%1,%2,%3},[%4];" \
        : "=r"(r0),"=r"(r1),"=r"(r2),"=r"(r3) : "r"(a))
#define LDSM4T(r0,r1,r2,r3,a) \
    asm volatile("ldmatrix.sync.aligned.m8n8.x4.trans.shared.b16 {%0,%1,%2,%3},[%4];" \
        : "=r"(r0),"=r"(r1),"=r"(r2),"=r"(r3) : "r"(a))
#define MMAH(c0,c1,c2,c3,a0,a1,a2,a3,b0,b1) \
    asm("mma.sync.aligned.m16n8k16.row.col.f32.f16.f16.f32 " \
        "{%0,%1,%2,%3},{%4,%5,%6,%7},{%8,%9},{%0,%1,%2,%3};" \
        : "+f"(c0),"+f"(c1),"+f"(c2),"+f"(c3) \
        : "r"(a0),"r"(a1),"r"(a2),"r"(a3),"r"(b0),"r"(b1))
#define MMAH16(d0,d1,a0,a1,a2,a3,b0,b1) \
    asm("mma.sync.aligned.m16n8k16.row.col.f16.f16.f16.f16 " \
        "{%0,%1},{%2,%3,%4,%5},{%6,%7},{%0,%1};" \
        : "+r"(d0),"+r"(d1) \
        : "r"(a0),"r"(a1),"r"(a2),"r"(a3),"r"(b0),"r"(b1))
#define CVTH2(d,hi,lo) asm("cvt.rn.f16x2.f32 %0,%1,%2;" : "=r"(d) : "f"(hi),"f"(lo))
#define EX2H2(d,s) asm("ex2.approx.f16x2 %0,%1;" : "=r"(d) : "r"(s))
#define HADD2(d,a,b) asm("add.rn.f16x2 %0,%1,%2;" : "=r"(d) : "r"(a),"r"(b))
#define H2TOF2(lo,hi,v) \
    asm("{.reg .f16 l,h; mov.b32 {l,h}, %2; cvt.f32.f16 %0, l; cvt.f32.f16 %1, h;}" \
        : "=f"(lo), "=f"(hi) : "r"(v))
#define CPASYNC16(sa, ga) asm volatile("cp.async.cg.shared.global [%0],[%1],16;" :: "r"(sa),"l"(ga))
#define CPCOMMIT() asm volatile("cp.async.commit_group;" ::: "memory")
#define CPWAIT(n)  asm volatile("cp.async.wait_group %0;" :: "n"(n) : "memory")

// swizzle for 32-col 16-bit tiles (4 x 16B chunks per row)
__device__ __forceinline__ int swoff(int row, int chunk) {
    return row * 32 + (((chunk) ^ ((row >> 1) & 3)) << 3);
}
// swizzle for 128-col 16-bit tiles (16 x 16B chunks per row)
__device__ __forceinline__ int swoff2(int row, int chunk) {
    return row * 128 + ((((chunk ^ row) & 7) | (chunk & 8)) << 3);
}

// ---------------- 0) prep: W->fp16 (blocks 0..191) + xsum (192..255) ------
__global__ void __launch_bounds__(256) prep_kernel(
    const float* __restrict__ x,
    const float* __restrict__ Wk,
    const float* __restrict__ Wq,
    const float* __restrict__ Wv)
{
    if (blockIdx.x < 192) {
        int idx = blockIdx.x * 256 + threadIdx.x;   // 0..49151
        int mat = idx >> 14;
        int rem = idx & 16383;
        const float* W = (mat == 0) ? Wq : (mat == 1) ? Wk : Wv;
        float scale = (mat == 0) ? (QSCALE * LOG2E) : 1.0f;
        g_wh[idx] = __float2half(W[rem] * scale);
    } else {
        int blk = blockIdx.x - 192;      // 0..63 : b*32 + part
        int d = threadIdx.x & 127;
        int c = threadIdx.x >> 7;        // 0..1
        int b = blk >> 5, part = blk & 31;
        size_t rbase = (size_t)b * SS + part * 128;
        const float* base = x + rbase * DD;
        __half* xb = g_xh + rbase * DD;
        float s = 0.f;
        for (int j = c; j < 128; j += 2) {
            float v = base[(size_t)j * DD + d];
            s += v;
            xb[(size_t)j * DD + d] = __float2half(v);
        }
        __shared__ float red[2][DD];
        red[c][d] = s;
        __syncthreads();
        if (c == 0)
            g_xpart[blk][d] = red[0][d] + red[1][d];
    }
}

// ---------------- 1) vsum = W_V . xsum (fp32 exact) -----------------------
__global__ void __launch_bounds__(128) vsumw_kernel(const float* __restrict__ Wv)
{
    int bh = blockIdx.x;
    int b = bh >> 2, h = bh & 3;
    __shared__ float xs[DD];
    int tid = threadIdx.x;
    if (tid < DD) {
        float s = 0.f;
#pragma unroll
        for (int p = 0; p < 32; p++) s += g_xpart[b * 32 + p][tid];
        xs[tid] = s;
    }
    __syncthreads();
    if (tid < DH) {
        const float* Wr = Wv + (size_t)(h * DH + tid) * DD;
        float s = 0.f;
#pragma unroll 4
        for (int j = 0; j < DD; j++) s = fmaf(Wr[j], xs[j], s);
        g_vsum[bh * DH + tid] = s;
    }
}

// ---------------- 2) QKV projection via tensor cores (fp16) ---------------
__global__ void __launch_bounds__(128) projmma_kernel()
{
    int bx = blockIdx.x;
    int rowbase = blockIdx.y * 64;
    int mat = bx >> 1;
    int obase = (bx & 1) * 64;
    int tid = threadIdx.x;
    int w = tid >> 5, lane = tid & 31;
    int lrow = lane & 15, lchunk = lane >> 4;
    int r = lane >> 2, cq = lane & 3;

    __shared__ __align__(16) __half sX[64 * 128];
    __shared__ __align__(16) __half sW[64 * 128];

    const uint4* gX = (const uint4*)(g_xh + (size_t)rowbase * DD);
    const uint4* gW = (const uint4*)(g_wh + (size_t)(mat * 128 + obase) * 128);
    for (int i = tid; i < 1024; i += 128) {
        int row = i >> 4, c = i & 15;
        int off = swoff2(row, c);
        CPASYNC16(smaddr(sX + off), gX + i);
        CPASYNC16(smaddr(sW + off), gW + i);
    }
    CPCOMMIT();
    CPWAIT(0);
    __syncthreads();

    int wr = (w >> 1) * 32, wc = (w & 1) * 32;
    float acc[2][4][4];
#pragma unroll
    for (int i = 0; i < 2; i++)
#pragma unroll
        for (int j = 0; j < 4; j++)
#pragma unroll
            for (int k = 0; k < 4; k++) acc[i][j][k] = 0.f;

#pragma unroll
    for (int ks = 0; ks < 8; ks++) {
        u32 a0[4], a1[4], b0[4], b1[4];
        LDSM4(a0[0], a0[1], a0[2], a0[3], smaddr(sX + swoff2(wr + lrow,      2 * ks + lchunk)));
        LDSM4(a1[0], a1[1], a1[2], a1[3], smaddr(sX + swoff2(wr + 16 + lrow, 2 * ks + lchunk)));
        LDSM4(b0[0], b0[1], b0[2], b0[3], smaddr(sW + swoff2(wc + lrow,      2 * ks + lchunk)));
        LDSM4(b1[0], b1[1], b1[2], b1[3], smaddr(sW + swoff2(wc + 16 + lrow, 2 * ks + lchunk)));
        MMAH(acc[0][0][0], acc[0][0][1], acc[0][0][2], acc[0][0][3], a0[0], a0[1], a0[2], a0[3], b0[0], b0[2]);
        MMAH(acc[0][1][0], acc[0][1][1], acc[0][1][2], acc[0][1][3], a0[0], a0[1], a0[2], a0[3], b0[1], b0[3]);
        MMAH(acc[0][2][0], acc[0][2][1], acc[0][2][2], acc[0][2][3], a0[0], a0[1], a0[2], a0[3], b1[0], b1[2]);
        MMAH(acc[0][3][0], acc[0][3][1], acc[0][3][2], acc[0][3][3], a0[0], a0[1], a0[2], a0[3], b1[1], b1[3]);
        MMAH(acc[1][0][0], acc[1][0][1], acc[1][0][2], acc[1][0][3], a1[0], a1[1], a1[2], a1[3], b0[0], b0[2]);
        MMAH(acc[1][1][0], acc[1][1][1], acc[1][1][2], acc[1][1][3], a1[0], a1[1], a1[2], a1[3], b0[1], b0[3]);
        MMAH(acc[1][2][0], acc[1][2][1], acc[1][2][2], acc[1][2][3], a1[0], a1[1], a1[2], a1[3], b1[0], b1[2]);
        MMAH(acc[1][3][0], acc[1][3][1], acc[1][3][2], acc[1][3][3], a1[0], a1[1], a1[2], a1[3], b1[1], b1[3]);
    }

    __half* G = (mat == 0) ? g_qh : (mat == 1) ? g_kh : g_vh;
#pragma unroll
    for (int rg = 0; rg < 2; rg++) {
#pragma unroll
        for (int ng = 0; ng < 4; ng++) {
            int co = obase + wc + ng * 8 + 2 * cq;   // 0..127 within matrix
            int h = co >> 5, d = co & 31;
            int prow0 = rowbase + wr + rg * 16 + r;
            int b = prow0 >> 12, pp = prow0 & 4095;
            size_t base0 = ((size_t)((b * HH + h)) * SS + pp) * DH + d;
            u32 pk0; CVTH2(pk0, acc[rg][ng][1], acc[rg][ng][0]);
            *(u32*)(G + base0) = pk0;
            u32 pk1; CVTH2(pk1, acc[rg][ng][3], acc[rg][ng][2]);
            *(u32*)(G + base0 + (size_t)8 * DH) = pk1;
        }
    }
}

// ---------------- 3) attention: 64 q/warp (4 groups), single wave ---------
// grid (BHT, SS/256, KS) = 512 CTAs, 128 threads (4 warps x 64 queries)
__global__ void __launch_bounds__(128, 4) attn_kernel()
{
    int bh = blockIdx.x;
    int qt = blockIdx.y;                 // 256-query tile
    int ks = blockIdx.z;
    int tid = threadIdx.x;
    int w = tid >> 5, lane = tid & 31;
    int lrow = lane & 15, lchunk = lane >> 4;
    int r = lane >> 2, cq = lane & 3;

    __shared__ __align__(16) __half sK[2 * 64 * 32];
    __shared__ __align__(16) __half sV[2 * 64 * 32];

    // ---- stage Q tile in two 128-row halves, extract 4 groups per warp ----
    u32 qf[4][8];
    const uint4* gQ = (const uint4*)(g_qh + ((size_t)bh * SS + qt * 256) * DH);
#pragma unroll
    for (int half = 0; half < 2; half++) {
        for (int i = tid; i < 512; i += 128) {
            int row = i >> 2, c = i & 3;
            *(uint4*)(sK + swoff(row, c)) = gQ[half * 512 + i];
        }
        __syncthreads();
        if ((w >> 1) == half) {          // warps 0,1 use half 0; warps 2,3 half 1
            int wl = (w & 1) * 64;       // local 64-row band within this half
#pragma unroll
            for (int g = 0; g < 4; g++) {
                int row = wl + g * 16 + lrow;
                LDSM4(qf[g][0], qf[g][1], qf[g][2], qf[g][3], smaddr(sK + swoff(row, lchunk)));
                LDSM4(qf[g][4], qf[g][5], qf[g][6], qf[g][7], smaddr(sK + swoff(row, 2 + lchunk)));
            }
        }
        __syncthreads();
    }

    u32 oo[4][8];
#pragma unroll
    for (int g = 0; g < 4; g++)
#pragma unroll
        for (int i = 0; i < 8; i++) oo[g][i] = 0u;
    float lf[4][2];
#pragma unroll
    for (int g = 0; g < 4; g++) { lf[g][0] = 0.f; lf[g][1] = 0.f; }

    const int kbase = ks * (SS / KS);               // 1024 keys per split
    const __half* gK = g_kh + ((size_t)bh * SS + kbase) * DH;
    const __half* gV = g_vh + ((size_t)bh * SS + kbase) * DH;
    const int NCH = SS / KS / 64;                   // 16 chunks of 64 keys

    // prefetch chunk 0
    {
        const uint4* srcK = (const uint4*)gK;
        const uint4* srcV = (const uint4*)gV;
        for (int i = tid; i < 256; i += 128) {
            int row = i >> 2, c = i & 3;
            int off = swoff(row, c);
            CPASYNC16(smaddr(sK + off), srcK + i);
            CPASYNC16(smaddr(sV + off), srcV + i);
        }
        CPCOMMIT();
    }

    for (int ch = 0; ch < NCH; ch++) {
        int bufoff = (ch & 1) * 2048;
        if (ch + 1 < NCH) {
            const uint4* srcK = (const uint4*)(gK + (size_t)(ch + 1) * 64 * DH);
            const uint4* srcV = (const uint4*)(gV + (size_t)(ch + 1) * 64 * DH);
            int nboff = ((ch + 1) & 1) * 2048;
            for (int i = tid; i < 256; i += 128) {
                int row = i >> 2, c = i & 3;
                int off = nboff + swoff(row, c);
                CPASYNC16(smaddr(sK + off), srcK + i);
                CPASYNC16(smaddr(sV + off), srcV + i);
            }
            CPCOMMIT();
            CPWAIT(1);
        } else {
            CPWAIT(0);
        }
        __syncthreads();

        u32 hl[4][2];
#pragma unroll
        for (int g = 0; g < 4; g++) { hl[g][0] = 0u; hl[g][1] = 0u; }

#pragma unroll
        for (int kt = 0; kt < 4; kt++) {            // 16 keys per step
            int row = kt * 16 + lrow;
            u32 k0[4], k1[4], v0[4], v1[4];
            LDSM4 (k0[0], k0[1], k0[2], k0[3], smaddr(sK + bufoff + swoff(row, lchunk)));
            LDSM4 (k1[0], k1[1], k1[2], k1[3], smaddr(sK + bufoff + swoff(row, 2 + lchunk)));
            LDSM4T(v0[0], v0[1], v0[2], v0[3], smaddr(sV + bufoff + swoff(row, lchunk)));
            LDSM4T(v1[0], v1[1], v1[2], v1[3], smaddr(sV + bufoff + swoff(row, 2 + lchunk)));

#pragma unroll
            for (int g = 0; g < 4; g++) {
                u32 s0 = 0u, s1 = 0u, t0 = 0u, t1 = 0u;
                MMAH16(s0, s1, qf[g][0], qf[g][1], qf[g][2], qf[g][3], k0[0], k0[2]);
                MMAH16(s0, s1, qf[g][4], qf[g][5], qf[g][6], qf[g][7], k1[0], k1[2]);
                MMAH16(t0, t1, qf[g][0], qf[g][1], qf[g][2], qf[g][3], k0[1], k0[3]);
                MMAH16(t0, t1, qf[g][4], qf[g][5], qf[g][6], qf[g][7], k1[1], k1[3]);
                EX2H2(s0, s0); EX2H2(s1, s1); EX2H2(t0, t0); EX2H2(t1, t1);
                HADD2(hl[g][0], hl[g][0], s0); HADD2(hl[g][0], hl[g][0], t0);
                HADD2(hl[g][1], hl[g][1], s1); HADD2(hl[g][1], hl[g][1], t1);
                MMAH16(oo[g][0], oo[g][1], s0, s1, t0, t1, v0[0], v0[1]);
                MMAH16(oo[g][2], oo[g][3], s0, s1, t0, t1, v0[2], v0[3]);
                MMAH16(oo[g][4], oo[g][5], s0, s1, t0, t1, v1[0], v1[1]);
                MMAH16(oo[g][6], oo[g][7], s0, s1, t0, t1, v1[2], v1[3]);
            }
        }

        // flush packed-l to f32
#pragma unroll
        for (int g = 0; g < 4; g++) {
            float lo, hi;
            H2TOF2(lo, hi, hl[g][0]); lf[g][0] += lo + hi;
            H2TOF2(lo, hi, hl[g][1]); lf[g][1] += lo + hi;
        }
        __syncthreads();
    }

    // l reduction across row-quads + stores
#pragma unroll
    for (int g = 0; g < 4; g++) {
        float l0 = lf[g][0], l1 = lf[g][1];
        l0 += __shfl_xor_sync(0xffffffffu, l0, 1);
        l0 += __shfl_xor_sync(0xffffffffu, l0, 2);
        l1 += __shfl_xor_sync(0xffffffffu, l1, 1);
        l1 += __shfl_xor_sync(0xffffffffu, l1, 2);
        int qg = qt * 256 + w * 64 + g * 16 + r;
        if (cq == 0) {
            g_lpart[((size_t)bh * SS + qg) * KS + ks]     = l0;
            g_lpart[((size_t)bh * SS + qg + 8) * KS + ks] = l1;
        }
#pragma unroll
        for (int d = 0; d < 4; d++) {
            *(u32*)(g_oparth + (((size_t)bh * SS + qg)     * KS + ks) * DH + d * 8 + cq * 2) = oo[g][d * 2 + 0];
            *(u32*)(g_oparth + (((size_t)bh * SS + qg + 8) * KS + ks) * DH + d * 8 + cq * 2) = oo[g][d * 2 + 1];
        }
    }
}

// ---------------- 4) fused combine + output projection (256 threads) ------
__global__ void __launch_bounds__(256) outfused_kernel(
    const float* __restrict__ Wo, float* __restrict__ out)
{
    const int R = 16;
    __shared__ __align__(16) float zs[R][DD];
    __shared__ float ls[R][HH];
    int rowbase = blockIdx.x * R;
    int tid = threadIdx.x;

    // phase A: per-(row, head) inverse-l
    if (tid < R * HH) {
        int rr = tid >> 2, h = tid & 3;
        int grow = rowbase + rr;
        int b = grow >> 12, p = grow & 4095;
        int bh = b * HH + h;
        float l = 0.f;
#pragma unroll
        for (int k = 0; k < KS; k++) l += g_lpart[((size_t)bh * SS + p) * KS + k];
        ls[rr][h] = 0.5f / l;
    }
    __syncthreads();

    // phase B: build z tile (512 4-wide chunks over 256 threads)
#pragma unroll
    for (int rr4 = 0; rr4 < 2; rr4++) {
        int e = rr4 * 256 + tid;          // 0..511
        int row = e >> 5, fq = e & 31;
        int h = fq >> 3, dq = fq & 7;
        int grow = rowbase + row;
        int b = grow >> 12, p = grow & 4095;
        int bh = b * HH + h;
        float ox = 0.f, oy = 0.f, oz = 0.f, ow = 0.f;
#pragma unroll
        for (int k = 0; k < KS; k++) {
            uint2 t = ((const uint2*)(g_oparth + (((size_t)bh * SS + p) * KS + k) * DH))[dq];
            float2 lo = __half22float2(*(const __half2*)&t.x);
            float2 hi = __half22float2(*(const __half2*)&t.y);
            ox += lo.x; oy += lo.y; oz += hi.x; ow += hi.y;
        }
        float inv = ls[row][h];
        float4 vs = ((const float4*)(g_vsum + bh * DH))[dq];
        float4 z;
        z.x = fmaf(ox, inv, 0.5f * vs.x);
        z.y = fmaf(oy, inv, 0.5f * vs.y);
        z.z = fmaf(oz, inv, 0.5f * vs.z);
        z.w = fmaf(ow, inv, 0.5f * vs.w);
        *(float4*)(&zs[row][fq * 4]) = z;
    }
    __syncthreads();

    // phase C: out = z @ Wo^T ; 256 threads: col = tid&127, row-half = tid>>7
    int col = tid & 127;
    int rh = tid >> 7;           // 0 or 1: rows rh*8 .. rh*8+7
    const float4* Wr = (const float4*)(Wo + col * DD);
    float acc[8];
#pragma unroll
    for (int r = 0; r < 8; r++) acc[r] = 0.f;
#pragma unroll 8
    for (int jc = 0; jc < DD / 4; jc++) {
        float4 w = Wr[jc];
#pragma unroll
        for (int r = 0; r < 8; r++) {
            float4 zv = *(const float4*)(&zs[rh * 8 + r][jc * 4]);
            acc[r] = fmaf(w.x, zv.x, acc[r]);
            acc[r] = fmaf(w.y, zv.y, acc[r]);
            acc[r] = fmaf(w.z, zv.z, acc[r]);
            acc[r] = fmaf(w.w, zv.w, acc[r]);
        }
    }
#pragma unroll
    for (int r = 0; r < 8; r++)
        out[(size_t)(rowbase + rh * 8 + r) * DD + col] = acc[r];
}

// ---------------- launch ----------------
extern "C" void kernel_launch(void* const* d_in, const int* in_sizes, int n_in,
                              void* d_out, int out_size)
{
    const float* x  = (const float*)d_in[0];
    const float* Wk = (const float*)d_in[1];
    const float* Wq = (const float*)d_in[2];
    const float* Wv = (const float*)d_in[3];
    const float* Wo = (const float*)d_in[4];
    float* out = (float*)d_out;

    prep_kernel<<<256, 256>>>(x, Wk, Wq, Wv);
    vsumw_kernel<<<BHT, 128>>>(Wv);
    projmma_kernel<<<dim3(6, (BB * SS) / 64), 128>>>();
    {
        dim3 grid(BHT, SS / 256, KS);
        attn_kernel<<<grid, 128>>>();
    }
    outfused_kernel<<<(BB * SS) / 16, 256>>>(Wo, out);
}

// round 15
// speedup vs baseline: 1.1330x; 1.1330x over previous
#include <cuda_runtime.h>
#include <cuda_fp16.h>

#define BB 2
#define SS 4096
#define DD 128
#define HH 4
#define DH 32
#define BHT (BB*HH)
#define KS 4
#define QSCALE 0.17677669529663687f   // 1/sqrt(32)
#define LOG2E  1.4426950408889634f

typedef unsigned int u32;

// ---------------- scratch (device globals; no allocations) ----------------
__device__ __align__(16) __half g_qh[(size_t)BHT*SS*DH];
__device__ __align__(16) __half g_kh[(size_t)BHT*SS*DH];
__device__ __align__(16) __half g_vh[(size_t)BHT*SS*DH];
__device__ __align__(16) __half g_xh[(size_t)BB*SS*DD];
__device__ __align__(16) __half g_wh[3*128*128];
__device__ __align__(16) float g_xpart[BB*32][DD];
__device__ __align__(16) float g_vsum[BHT*DH];
__device__ __align__(16) float g_lpart[(size_t)BHT*SS*KS];
__device__ __align__(16) __half g_oparth[(size_t)BHT*SS*KS*DH];

// ---------------- asm helpers ----------------
__device__ __forceinline__ u32 smaddr(const void* p) {
    u32 a;
    asm("{.reg .u64 t; cvta.to.shared.u64 t, %1; cvt.u32.u64 %0, t;}" : "=r"(a) : "l"(p));
    return a;
}
#define LDSM4(r0,r1,r2,r3,a) \
    asm volatile("ldmatrix.sync.aligned.m8n8.x4.shared.b16 {%0,%1,%2,%3},[%4];" \
        : "=r"(r0),"=r"(r1),"=r"(r2),"=r"(r3) : "r"(a))
#define LDSM4T(r0,r1,r2,r3,a) \
    asm volatile("ldmatrix.sync.aligned.m8n8.x4.trans.shared.b16 {%0,%1,%2,%3},[%4];" \
        : "=r"(r0),"=r"(r1),"=r"(r2),"=r"(r3) : "r"(a))
#define MMAH(c0,c1,c2,c3,a0,a1,a2,a3,b0,b1) \
    asm("mma.sync.aligned.m16n8k16.row.col.f32.f16.f16.f32 " \
        "{%0,%1,%2,%3},{%4,%5,%6,%7},{%8,%9},{%0,%1,%2,%3};" \
        : "+f"(c0),"+f"(c1),"+f"(c2),"+f"(c3) \
        : "r"(a0),"r"(a1),"r"(a2),"r"(a3),"r"(b0),"r"(b1))
#define MMAH16(d0,d1,a0,a1,a2,a3,b0,b1) \
    asm("mma.sync.aligned.m16n8k16.row.col.f16.f16.f16.f16 " \
        "{%0,%1},{%2,%3,%4,%5},{%6,%7},{%0,%1};" \
        : "+r"(d0),"+r"(d1) \
        : "r"(a0),"r"(a1),"r"(a2),"r"(a3),"r"(b0),"r"(b1))
#define CVTH2(d,hi,lo) asm("cvt.rn.f16x2.f32 %0,%1,%2;" : "=r"(d) : "f"(hi),"f"(lo))
#define EX2H2(d,s) asm("ex2.approx.f16x2 %0,%1;" : "=r"(d) : "r"(s))
#define HADD2(d,a,b) asm("add.rn.f16x2 %0,%1,%2;" : "=r"(d) : "r"(a),"r"(b))
#define H2TOF2(lo,hi,v) \
    asm("{.reg .f16 l,h; mov.b32 {l,h}, %2; cvt.f32.f16 %0, l; cvt.f32.f16 %1, h;}" \
        : "=f"(lo), "=f"(hi) : "r"(v))
#define CPASYNC16(sa, ga) asm volatile("cp.async.cg.shared.global [%0],[%1],16;" :: "r"(sa),"l"(ga))
#define CPCOMMIT() asm volatile("cp.async.commit_group;" ::: "memory")
#define CPWAIT(n)  asm volatile("cp.async.wait_group %0;" :: "n"(n) : "memory")

// swizzle for 32-col 16-bit tiles (4 x 16B chunks per row)
__device__ __forceinline__ int swoff(int row, int chunk) {
    return row * 32 + (((chunk) ^ ((row >> 1) & 3)) << 3);
}
// swizzle for 128-col 16-bit tiles (16 x 16B chunks per row)
__device__ __forceinline__ int swoff2(int row, int chunk) {
    return row * 128 + ((((chunk ^ row) & 7) | (chunk & 8)) << 3);
}

// ---------------- 0) prep: W->fp16 (blocks 0..191) + xsum (192..255) ------
__global__ void __launch_bounds__(256) prep_kernel(
    const float* __restrict__ x,
    const float* __restrict__ Wk,
    const float* __restrict__ Wq,
    const float* __restrict__ Wv)
{
    if (blockIdx.x < 192) {
        int idx = blockIdx.x * 256 + threadIdx.x;   // 0..49151
        int mat = idx >> 14;
        int rem = idx & 16383;
        const float* W = (mat == 0) ? Wq : (mat == 1) ? Wk : Wv;
        float scale = (mat == 0) ? (QSCALE * LOG2E) : 1.0f;
        g_wh[idx] = __float2half(W[rem] * scale);
    } else {
        int blk = blockIdx.x - 192;      // 0..63 : b*32 + part
        int d = threadIdx.x & 127;
        int c = threadIdx.x >> 7;        // 0..1
        int b = blk >> 5, part = blk & 31;
        size_t rbase = (size_t)b * SS + part * 128;
        const float* base = x + rbase * DD;
        __half* xb = g_xh + rbase * DD;
        float s = 0.f;
        for (int j = c; j < 128; j += 2) {
            float v = base[(size_t)j * DD + d];
            s += v;
            xb[(size_t)j * DD + d] = __float2half(v);
        }
        __shared__ float red[2][DD];
        red[c][d] = s;
        __syncthreads();
        if (c == 0)
            g_xpart[blk][d] = red[0][d] + red[1][d];
    }
}

// ---------------- 1) vsum = W_V . xsum (fp32 exact) -----------------------
__global__ void __launch_bounds__(128) vsumw_kernel(const float* __restrict__ Wv)
{
    int bh = blockIdx.x;
    int b = bh >> 2, h = bh & 3;
    __shared__ float xs[DD];
    int tid = threadIdx.x;
    if (tid < DD) {
        float s = 0.f;
#pragma unroll
        for (int p = 0; p < 32; p++) s += g_xpart[b * 32 + p][tid];
        xs[tid] = s;
    }
    __syncthreads();
    if (tid < DH) {
        const float* Wr = Wv + (size_t)(h * DH + tid) * DD;
        float s = 0.f;
#pragma unroll 4
        for (int j = 0; j < DD; j++) s = fmaf(Wr[j], xs[j], s);
        g_vsum[bh * DH + tid] = s;
    }
}

// ---------------- 2) QKV projection via tensor cores (fp16) ---------------
__global__ void __launch_bounds__(128) projmma_kernel()
{
    int bx = blockIdx.x;
    int rowbase = blockIdx.y * 64;
    int mat = bx >> 1;
    int obase = (bx & 1) * 64;
    int tid = threadIdx.x;
    int w = tid >> 5, lane = tid & 31;
    int lrow = lane & 15, lchunk = lane >> 4;
    int r = lane >> 2, cq = lane & 3;

    __shared__ __align__(16) __half sX[64 * 128];
    __shared__ __align__(16) __half sW[64 * 128];

    const uint4* gX = (const uint4*)(g_xh + (size_t)rowbase * DD);
    const uint4* gW = (const uint4*)(g_wh + (size_t)(mat * 128 + obase) * 128);
    for (int i = tid; i < 1024; i += 128) {
        int row = i >> 4, c = i & 15;
        int off = swoff2(row, c);
        CPASYNC16(smaddr(sX + off), gX + i);
        CPASYNC16(smaddr(sW + off), gW + i);
    }
    CPCOMMIT();
    CPWAIT(0);
    __syncthreads();

    int wr = (w >> 1) * 32, wc = (w & 1) * 32;
    float acc[2][4][4];
#pragma unroll
    for (int i = 0; i < 2; i++)
#pragma unroll
        for (int j = 0; j < 4; j++)
#pragma unroll
            for (int k = 0; k < 4; k++) acc[i][j][k] = 0.f;

#pragma unroll
    for (int ks = 0; ks < 8; ks++) {
        u32 a0[4], a1[4], b0[4], b1[4];
        LDSM4(a0[0], a0[1], a0[2], a0[3], smaddr(sX + swoff2(wr + lrow,      2 * ks + lchunk)));
        LDSM4(a1[0], a1[1], a1[2], a1[3], smaddr(sX + swoff2(wr + 16 + lrow, 2 * ks + lchunk)));
        LDSM4(b0[0], b0[1], b0[2], b0[3], smaddr(sW + swoff2(wc + lrow,      2 * ks + lchunk)));
        LDSM4(b1[0], b1[1], b1[2], b1[3], smaddr(sW + swoff2(wc + 16 + lrow, 2 * ks + lchunk)));
        MMAH(acc[0][0][0], acc[0][0][1], acc[0][0][2], acc[0][0][3], a0[0], a0[1], a0[2], a0[3], b0[0], b0[2]);
        MMAH(acc[0][1][0], acc[0][1][1], acc[0][1][2], acc[0][1][3], a0[0], a0[1], a0[2], a0[3], b0[1], b0[3]);
        MMAH(acc[0][2][0], acc[0][2][1], acc[0][2][2], acc[0][2][3], a0[0], a0[1], a0[2], a0[3], b1[0], b1[2]);
        MMAH(acc[0][3][0], acc[0][3][1], acc[0][3][2], acc[0][3][3], a0[0], a0[1], a0[2], a0[3], b1[1], b1[3]);
        MMAH(acc[1][0][0], acc[1][0][1], acc[1][0][2], acc[1][0][3], a1[0], a1[1], a1[2], a1[3], b0[0], b0[2]);
        MMAH(acc[1][1][0], acc[1][1][1], acc[1][1][2], acc[1][1][3], a1[0], a1[1], a1[2], a1[3], b0[1], b0[3]);
        MMAH(acc[1][2][0], acc[1][2][1], acc[1][2][2], acc[1][2][3], a1[0], a1[1], a1[2], a1[3], b1[0], b1[2]);
        MMAH(acc[1][3][0], acc[1][3][1], acc[1][3][2], acc[1][3][3], a1[0], a1[1], a1[2], a1[3], b1[1], b1[3]);
    }

    __half* G = (mat == 0) ? g_qh : (mat == 1) ? g_kh : g_vh;
#pragma unroll
    for (int rg = 0; rg < 2; rg++) {
#pragma unroll
        for (int ng = 0; ng < 4; ng++) {
            int co = obase + wc + ng * 8 + 2 * cq;   // 0..127 within matrix
            int h = co >> 5, d = co & 31;
            int prow0 = rowbase + wr + rg * 16 + r;
            int b = prow0 >> 12, pp = prow0 & 4095;
            size_t base0 = ((size_t)((b * HH + h)) * SS + pp) * DH + d;
            u32 pk0; CVTH2(pk0, acc[rg][ng][1], acc[rg][ng][0]);
            *(u32*)(G + base0) = pk0;
            u32 pk1; CVTH2(pk1, acc[rg][ng][3], acc[rg][ng][2]);
            *(u32*)(G + base0 + (size_t)8 * DH) = pk1;
        }
    }
}

// ---------------- 3) attention: R8 body, reg cap for 6 CTAs/SM ------------
// grid (BHT, SS/128, KS), 128 threads (4 warps x 32 queries)
__global__ void __launch_bounds__(128, 6) attn_kernel()
{
    int bh = blockIdx.x;
    int qt = blockIdx.y;
    int ks = blockIdx.z;
    int tid = threadIdx.x;
    int w = tid >> 5, lane = tid & 31;
    int lrow = lane & 15, lchunk = lane >> 4;

    __shared__ __align__(16) __half sK[2 * 64 * 32];
    __shared__ __align__(16) __half sV[2 * 64 * 32];

    // ---- stage Q tile (128 rows fills both K buffers), extract fragments --
    {
        const uint4* gQ = (const uint4*)(g_qh + ((size_t)bh * SS + qt * 128) * DH);
        for (int i = tid; i < 512; i += 128) {
            int row = i >> 2, c = i & 3;
            *(uint4*)(sK + swoff(row, c)) = gQ[i];
        }
    }
    __syncthreads();
    u32 qf0[8], qf1[8];
    {
        int row0 = w * 32 + lrow;
        LDSM4(qf0[0], qf0[1], qf0[2], qf0[3], smaddr(sK + swoff(row0, lchunk)));
        LDSM4(qf0[4], qf0[5], qf0[6], qf0[7], smaddr(sK + swoff(row0, 2 + lchunk)));
        int row1 = row0 + 16;
        LDSM4(qf1[0], qf1[1], qf1[2], qf1[3], smaddr(sK + swoff(row1, lchunk)));
        LDSM4(qf1[4], qf1[5], qf1[6], qf1[7], smaddr(sK + swoff(row1, 2 + lchunk)));
    }
    __syncthreads();   // done reading Q before cp.async overwrites sK

    u32 oA[8], oB[8];
#pragma unroll
    for (int i = 0; i < 8; i++) { oA[i] = 0u; oB[i] = 0u; }
    float lA0 = 0.f, lA1 = 0.f, lB0 = 0.f, lB1 = 0.f;

    const int kbase = ks * (SS / KS);               // 1024 keys per split
    const __half* gK = g_kh + ((size_t)bh * SS + kbase) * DH;
    const __half* gV = g_vh + ((size_t)bh * SS + kbase) * DH;
    const int NCH = SS / KS / 64;                   // 16 chunks of 64 keys

    // prefetch chunk 0
    {
        const uint4* srcK = (const uint4*)gK;
        const uint4* srcV = (const uint4*)gV;
        for (int i = tid; i < 256; i += 128) {
            int row = i >> 2, c = i & 3;
            int off = swoff(row, c);
            CPASYNC16(smaddr(sK + off), srcK + i);
            CPASYNC16(smaddr(sV + off), srcV + i);
        }
        CPCOMMIT();
    }

    for (int ch = 0; ch < NCH; ch++) {
        int bufoff = (ch & 1) * 2048;
        if (ch + 1 < NCH) {
            const uint4* srcK = (const uint4*)(gK + (size_t)(ch + 1) * 64 * DH);
            const uint4* srcV = (const uint4*)(gV + (size_t)(ch + 1) * 64 * DH);
            int nboff = ((ch + 1) & 1) * 2048;
            for (int i = tid; i < 256; i += 128) {
                int row = i >> 2, c = i & 3;
                int off = nboff + swoff(row, c);
                CPASYNC16(smaddr(sK + off), srcK + i);
                CPASYNC16(smaddr(sV + off), srcV + i);
            }
            CPCOMMIT();
            CPWAIT(1);
        } else {
            CPWAIT(0);
        }
        __syncthreads();

        u32 hA0 = 0u, hA1 = 0u, hB0 = 0u, hB1 = 0u;

#pragma unroll
        for (int kt = 0; kt < 4; kt++) {            // 16 keys per step
            int row = kt * 16 + lrow;
            u32 k0[4], k1[4], v0[4], v1[4];
            LDSM4 (k0[0], k0[1], k0[2], k0[3], smaddr(sK + bufoff + swoff(row, lchunk)));
            LDSM4 (k1[0], k1[1], k1[2], k1[3], smaddr(sK + bufoff + swoff(row, 2 + lchunk)));
            LDSM4T(v0[0], v0[1], v0[2], v0[3], smaddr(sV + bufoff + swoff(row, lchunk)));
            LDSM4T(v1[0], v1[1], v1[2], v1[3], smaddr(sV + bufoff + swoff(row, 2 + lchunk)));

            // ---- group A (queries w*32 .. +15) ----
            u32 aA0 = 0u, aA1 = 0u, aB0 = 0u, aB1 = 0u;
            MMAH16(aA0, aA1, qf0[0], qf0[1], qf0[2], qf0[3], k0[0], k0[2]);
            MMAH16(aA0, aA1, qf0[4], qf0[5], qf0[6], qf0[7], k1[0], k1[2]);
            MMAH16(aB0, aB1, qf0[0], qf0[1], qf0[2], qf0[3], k0[1], k0[3]);
            MMAH16(aB0, aB1, qf0[4], qf0[5], qf0[6], qf0[7], k1[1], k1[3]);
            EX2H2(aA0, aA0); EX2H2(aA1, aA1); EX2H2(aB0, aB0); EX2H2(aB1, aB1);
            HADD2(hA0, hA0, aA0); HADD2(hA0, hA0, aB0);
            HADD2(hA1, hA1, aA1); HADD2(hA1, hA1, aB1);
            MMAH16(oA[0], oA[1], aA0, aA1, aB0, aB1, v0[0], v0[1]);
            MMAH16(oA[2], oA[3], aA0, aA1, aB0, aB1, v0[2], v0[3]);
            MMAH16(oA[4], oA[5], aA0, aA1, aB0, aB1, v1[0], v1[1]);
            MMAH16(oA[6], oA[7], aA0, aA1, aB0, aB1, v1[2], v1[3]);

            // ---- group B (queries w*32+16 .. +31) ----
            u32 bA0 = 0u, bA1 = 0u, bB0 = 0u, bB1 = 0u;
            MMAH16(bA0, bA1, qf1[0], qf1[1], qf1[2], qf1[3], k0[0], k0[2]);
            MMAH16(bA0, bA1, qf1[4], qf1[5], qf1[6], qf1[7], k1[0], k1[2]);
            MMAH16(bB0, bB1, qf1[0], qf1[1], qf1[2], qf1[3], k0[1], k0[3]);
            MMAH16(bB0, bB1, qf1[4], qf1[5], qf1[6], qf1[7], k1[1], k1[3]);
            EX2H2(bA0, bA0); EX2H2(bA1, bA1); EX2H2(bB0, bB0); EX2H2(bB1, bB1);
            HADD2(hB0, hB0, bA0); HADD2(hB0, hB0, bB0);
            HADD2(hB1, hB1, bA1); HADD2(hB1, hB1, bB1);
            MMAH16(oB[0], oB[1], bA0, bA1, bB0, bB1, v0[0], v0[1]);
            MMAH16(oB[2], oB[3], bA0, bA1, bB0, bB1, v0[2], v0[3]);
            MMAH16(oB[4], oB[5], bA0, bA1, bB0, bB1, v1[0], v1[1]);
            MMAH16(oB[6], oB[7], bA0, bA1, bB0, bB1, v1[2], v1[3]);
        }

        // flush packed-l to f32
        {
            float lo, hi;
            H2TOF2(lo, hi, hA0); lA0 += lo + hi;
            H2TOF2(lo, hi, hA1); lA1 += lo + hi;
            H2TOF2(lo, hi, hB0); lB0 += lo + hi;
            H2TOF2(lo, hi, hB1); lB1 += lo + hi;
        }
        __syncthreads();
    }

    // l reduction across row-quads
    lA0 += __shfl_xor_sync(0xffffffffu, lA0, 1);
    lA0 += __shfl_xor_sync(0xffffffffu, lA0, 2);
    lA1 += __shfl_xor_sync(0xffffffffu, lA1, 1);
    lA1 += __shfl_xor_sync(0xffffffffu, lA1, 2);
    lB0 += __shfl_xor_sync(0xffffffffu, lB0, 1);
    lB0 += __shfl_xor_sync(0xffffffffu, lB0, 2);
    lB1 += __shfl_xor_sync(0xffffffffu, lB1, 1);
    lB1 += __shfl_xor_sync(0xffffffffu, lB1, 2);

    int r = lane >> 2, cq = lane & 3;
    int qgA = qt * 128 + w * 32 + r;
    int qgB = qgA + 16;
    if (cq == 0) {
        g_lpart[((size_t)bh * SS + qgA) * KS + ks]     = lA0;
        g_lpart[((size_t)bh * SS + qgA + 8) * KS + ks] = lA1;
        g_lpart[((size_t)bh * SS + qgB) * KS + ks]     = lB0;
        g_lpart[((size_t)bh * SS + qgB + 8) * KS + ks] = lB1;
    }
#pragma unroll
    for (int d = 0; d < 4; d++) {
        *(u32*)(g_oparth + (((size_t)bh * SS + qgA)     * KS + ks) * DH + d * 8 + cq * 2) = oA[d * 2 + 0];
        *(u32*)(g_oparth + (((size_t)bh * SS + qgA + 8) * KS + ks) * DH + d * 8 + cq * 2) = oA[d * 2 + 1];
        *(u32*)(g_oparth + (((size_t)bh * SS + qgB)     * KS + ks) * DH + d * 8 + cq * 2) = oB[d * 2 + 0];
        *(u32*)(g_oparth + (((size_t)bh * SS + qgB + 8) * KS + ks) * DH + d * 8 + cq * 2) = oB[d * 2 + 1];
    }
}

// ---------------- 4) fused combine + output projection (scalar, R8) -------
__global__ void __launch_bounds__(128) outfused_kernel(
    const float* __restrict__ Wo, float* __restrict__ out)
{
    const int R = 16;
    __shared__ __align__(16) float zs[R][DD];
    __shared__ float ls[R][HH];
    int rowbase = blockIdx.x * R;
    int tid = threadIdx.x;

    // phase A: per-(row, head) inverse-l
    if (tid < R * HH) {
        int rr = tid >> 2, h = tid & 3;
        int grow = rowbase + rr;
        int b = grow >> 12, p = grow & 4095;
        int bh = b * HH + h;
        float l = 0.f;
#pragma unroll
        for (int k = 0; k < KS; k++) l += g_lpart[((size_t)bh * SS + p) * KS + k];
        ls[rr][h] = 0.5f / l;
    }
    __syncthreads();

    // phase B: build z tile
#pragma unroll
    for (int rr4 = 0; rr4 < 4; rr4++) {
        int e = rr4 * 128 + tid;          // 0..511 : 4-wide d chunk
        int row = e >> 5, fq = e & 31;
        int h = fq >> 3, dq = fq & 7;
        int grow = rowbase + row;
        int b = grow >> 12, p = grow & 4095;
        int bh = b * HH + h;
        float ox = 0.f, oy = 0.f, oz = 0.f, ow = 0.f;
#pragma unroll
        for (int k = 0; k < KS; k++) {
            uint2 t = ((const uint2*)(g_oparth + (((size_t)bh * SS + p) * KS + k) * DH))[dq];
            float2 lo = __half22float2(*(const __half2*)&t.x);
            float2 hi = __half22float2(*(const __half2*)&t.y);
            ox += lo.x; oy += lo.y; oz += hi.x; ow += hi.y;
        }
        float inv = ls[row][h];
        float4 vs = ((const float4*)(g_vsum + bh * DH))[dq];
        float4 z;
        z.x = fmaf(ox, inv, 0.5f * vs.x);
        z.y = fmaf(oy, inv, 0.5f * vs.y);
        z.z = fmaf(oz, inv, 0.5f * vs.z);
        z.w = fmaf(ow, inv, 0.5f * vs.w);
        *(float4*)(&zs[row][fq * 4]) = z;
    }
    __syncthreads();

    // phase C: out = z @ Wo^T
    const float4* Wr = (const float4*)(Wo + tid * DD);
    float acc[R];
#pragma unroll
    for (int r = 0; r < R; r++) acc[r] = 0.f;
#pragma unroll 8
    for (int jc = 0; jc < DD / 4; jc++) {
        float4 w = Wr[jc];
#pragma unroll
        for (int r = 0; r < R; r++) {
            float4 zv = *(const float4*)(&zs[r][jc * 4]);
            acc[r] = fmaf(w.x, zv.x, acc[r]);
            acc[r] = fmaf(w.y, zv.y, acc[r]);
            acc[r] = fmaf(w.z, zv.z, acc[r]);
            acc[r] = fmaf(w.w, zv.w, acc[r]);
        }
    }
#pragma unroll
    for (int r = 0; r < R; r++)
        out[(size_t)(rowbase + r) * DD + tid] = acc[r];
}

// ---------------- launch ----------------
extern "C" void kernel_launch(void* const* d_in, const int* in_sizes, int n_in,
                              void* d_out, int out_size)
{
    const float* x  = (const float*)d_in[0];
    const float* Wk = (const float*)d_in[1];
    const float* Wq = (const float*)d_in[2];
    const float* Wv = (const float*)d_in[3];
    const float* Wo = (const float*)d_in[4];
    float* out = (float*)d_out;

    prep_kernel<<<256, 256>>>(x, Wk, Wq, Wv);
    vsumw_kernel<<<BHT, 128>>>(Wv);
    projmma_kernel<<<dim3(6, (BB * SS) / 64), 128>>>();
    {
        dim3 grid(BHT, SS / 128, KS);
        attn_kernel<<<grid, 128>>>();
    }
    outfused_kernel<<<(BB * SS) / 16, 128>>>(Wo, out);
}

// round 17
// speedup vs baseline: 1.2429x; 1.0970x over previous
#include <cuda_runtime.h>
#include <cuda_fp16.h>

#define BB 2
#define SS 4096
#define DD 128
#define HH 4
#define DH 32
#define BHT (BB*HH)
#define KS 4
#define QSCALE 0.17677669529663687f   // 1/sqrt(32)
#define LOG2E  1.4426950408889634f
#define ONESH2 0x3C003C00u            // f16x2 {1.0, 1.0}

typedef unsigned int u32;

// ---------------- scratch (device globals; no allocations) ----------------
__device__ __align__(16) __half g_qh[(size_t)BHT*SS*DH];
__device__ __align__(16) __half g_kh[(size_t)BHT*SS*DH];
__device__ __align__(16) __half g_vh[(size_t)BHT*SS*DH];
__device__ __align__(16) __half g_xh[(size_t)BB*SS*DD];
__device__ __align__(16) __half g_wh[3*128*128];
__device__ __align__(16) float g_xpart[BB*32][DD];
__device__ __align__(16) float g_vsum[BHT*DH];
__device__ __align__(16) float g_lpart[(size_t)BHT*SS*KS];
__device__ __align__(16) __half g_oparth[(size_t)BHT*SS*KS*DH];

// ---------------- asm helpers ----------------
__device__ __forceinline__ u32 smaddr(const void* p) {
    u32 a;
    asm("{.reg .u64 t; cvta.to.shared.u64 t, %1; cvt.u32.u64 %0, t;}" : "=r"(a) : "l"(p));
    return a;
}
#define LDSM4(r0,r1,r2,r3,a) \
    asm volatile("ldmatrix.sync.aligned.m8n8.x4.shared.b16 {%0,%1,%2,%3},[%4];" \
        : "=r"(r0),"=r"(r1),"=r"(r2),"=r"(r3) : "r"(a))
#define LDSM4T(r0,r1,r2,r3,a) \
    asm volatile("ldmatrix.sync.aligned.m8n8.x4.trans.shared.b16 {%0,%1,%2,%3},[%4];" \
        : "=r"(r0),"=r"(r1),"=r"(r2),"=r"(r3) : "r"(a))
#define MMAH(c0,c1,c2,c3,a0,a1,a2,a3,b0,b1) \
    asm("mma.sync.aligned.m16n8k16.row.col.f32.f16.f16.f32 " \
        "{%0,%1,%2,%3},{%4,%5,%6,%7},{%8,%9},{%0,%1,%2,%3};" \
        : "+f"(c0),"+f"(c1),"+f"(c2),"+f"(c3) \
        : "r"(a0),"r"(a1),"r"(a2),"r"(a3),"r"(b0),"r"(b1))
#define MMAH16(d0,d1,a0,a1,a2,a3,b0,b1) \
    asm("mma.sync.aligned.m16n8k16.row.col.f16.f16.f16.f16 " \
        "{%0,%1},{%2,%3,%4,%5},{%6,%7},{%0,%1};" \
        : "+r"(d0),"+r"(d1) \
        : "r"(a0),"r"(a1),"r"(a2),"r"(a3),"r"(b0),"r"(b1))
#define CVTH2(d,hi,lo) asm("cvt.rn.f16x2.f32 %0,%1,%2;" : "=r"(d) : "f"(hi),"f"(lo))
#define EX2H2(d,s) asm("ex2.approx.f16x2 %0,%1;" : "=r"(d) : "r"(s))
#define H2TOF2(lo,hi,v) \
    asm("{.reg .f16 l,h; mov.b32 {l,h}, %2; cvt.f32.f16 %0, l; cvt.f32.f16 %1, h;}" \
        : "=f"(lo), "=f"(hi) : "r"(v))
#define CPASYNC16(sa, ga) asm volatile("cp.async.cg.shared.global [%0],[%1],16;" :: "r"(sa),"l"(ga))
#define CPCOMMIT() asm volatile("cp.async.commit_group;" ::: "memory")
#define CPWAIT(n)  asm volatile("cp.async.wait_group %0;" :: "n"(n) : "memory")

// swizzle for 32-col 16-bit tiles (4 x 16B chunks per row)
__device__ __forceinline__ int swoff(int row, int chunk) {
    return row * 32 + (((chunk) ^ ((row >> 1) & 3)) << 3);
}
// swizzle for 128-col 16-bit tiles (16 x 16B chunks per row)
__device__ __forceinline__ int swoff2(int row, int chunk) {
    return row * 128 + ((((chunk ^ row) & 7) | (chunk & 8)) << 3);
}

// ---------------- 0) prep: W->fp16 (blocks 0..191) + xsum (192..255) ------
__global__ void __launch_bounds__(256) prep_kernel(
    const float* __restrict__ x,
    const float* __restrict__ Wk,
    const float* __restrict__ Wq,
    const float* __restrict__ Wv)
{
    if (blockIdx.x < 192) {
        int idx = blockIdx.x * 256 + threadIdx.x;   // 0..49151
        int mat = idx >> 14;
        int rem = idx & 16383;
        const float* W = (mat == 0) ? Wq : (mat == 1) ? Wk : Wv;
        float scale = (mat == 0) ? (QSCALE * LOG2E) : 1.0f;
        g_wh[idx] = __float2half(W[rem] * scale);
    } else {
        int blk = blockIdx.x - 192;      // 0..63 : b*32 + part
        int d = threadIdx.x & 127;
        int c = threadIdx.x >> 7;        // 0..1
        int b = blk >> 5, part = blk & 31;
        size_t rbase = (size_t)b * SS + part * 128;
        const float* base = x + rbase * DD;
        __half* xb = g_xh + rbase * DD;
        float s = 0.f;
        for (int j = c; j < 128; j += 2) {
            float v = base[(size_t)j * DD + d];
            s += v;
            xb[(size_t)j * DD + d] = __float2half(v);
        }
        __shared__ float red[2][DD];
        red[c][d] = s;
        __syncthreads();
        if (c == 0)
            g_xpart[blk][d] = red[0][d] + red[1][d];
    }
}

// ---------------- 1) vsum = W_V . xsum (fp32 exact) -----------------------
__global__ void __launch_bounds__(128) vsumw_kernel(const float* __restrict__ Wv)
{
    int bh = blockIdx.x;
    int b = bh >> 2, h = bh & 3;
    __shared__ float xs[DD];
    int tid = threadIdx.x;
    if (tid < DD) {
        float s = 0.f;
#pragma unroll
        for (int p = 0; p < 32; p++) s += g_xpart[b * 32 + p][tid];
        xs[tid] = s;
    }
    __syncthreads();
    if (tid < DH) {
        const float* Wr = Wv + (size_t)(h * DH + tid) * DD;
        float s = 0.f;
#pragma unroll 4
        for (int j = 0; j < DD; j++) s = fmaf(Wr[j], xs[j], s);
        g_vsum[bh * DH + tid] = s;
    }
}

// ---------------- 2) QKV projection via tensor cores (fp16) ---------------
__global__ void __launch_bounds__(128) projmma_kernel()
{
    int bx = blockIdx.x;
    int rowbase = blockIdx.y * 64;
    int mat = bx >> 1;
    int obase = (bx & 1) * 64;
    int tid = threadIdx.x;
    int w = tid >> 5, lane = tid & 31;
    int lrow = lane & 15, lchunk = lane >> 4;
    int r = lane >> 2, cq = lane & 3;

    __shared__ __align__(16) __half sX[64 * 128];
    __shared__ __align__(16) __half sW[64 * 128];

    const uint4* gX = (const uint4*)(g_xh + (size_t)rowbase * DD);
    const uint4* gW = (const uint4*)(g_wh + (size_t)(mat * 128 + obase) * 128);
    for (int i = tid; i < 1024; i += 128) {
        int row = i >> 4, c = i & 15;
        int off = swoff2(row, c);
        CPASYNC16(smaddr(sX + off), gX + i);
        CPASYNC16(smaddr(sW + off), gW + i);
    }
    CPCOMMIT();
    CPWAIT(0);
    __syncthreads();

    int wr = (w >> 1) * 32, wc = (w & 1) * 32;
    float acc[2][4][4];
#pragma unroll
    for (int i = 0; i < 2; i++)
#pragma unroll
        for (int j = 0; j < 4; j++)
#pragma unroll
            for (int k = 0; k < 4; k++) acc[i][j][k] = 0.f;

#pragma unroll
    for (int ks = 0; ks < 8; ks++) {
        u32 a0[4], a1[4], b0[4], b1[4];
        LDSM4(a0[0], a0[1], a0[2], a0[3], smaddr(sX + swoff2(wr + lrow,      2 * ks + lchunk)));
        LDSM4(a1[0], a1[1], a1[2], a1[3], smaddr(sX + swoff2(wr + 16 + lrow, 2 * ks + lchunk)));
        LDSM4(b0[0], b0[1], b0[2], b0[3], smaddr(sW + swoff2(wc + lrow,      2 * ks + lchunk)));
        LDSM4(b1[0], b1[1], b1[2], b1[3], smaddr(sW + swoff2(wc + 16 + lrow, 2 * ks + lchunk)));
        MMAH(acc[0][0][0], acc[0][0][1], acc[0][0][2], acc[0][0][3], a0[0], a0[1], a0[2], a0[3], b0[0], b0[2]);
        MMAH(acc[0][1][0], acc[0][1][1], acc[0][1][2], acc[0][1][3], a0[0], a0[1], a0[2], a0[3], b0[1], b0[3]);
        MMAH(acc[0][2][0], acc[0][2][1], acc[0][2][2], acc[0][2][3], a0[0], a0[1], a0[2], a0[3], b1[0], b1[2]);
        MMAH(acc[0][3][0], acc[0][3][1], acc[0][3][2], acc[0][3][3], a0[0], a0[1], a0[2], a0[3], b1[1], b1[3]);
        MMAH(acc[1][0][0], acc[1][0][1], acc[1][0][2], acc[1][0][3], a1[0], a1[1], a1[2], a1[3], b0[0], b0[2]);
        MMAH(acc[1][1][0], acc[1][1][1], acc[1][1][2], acc[1][1][3], a1[0], a1[1], a1[2], a1[3], b0[1], b0[3]);
        MMAH(acc[1][2][0], acc[1][2][1], acc[1][2][2], acc[1][2][3], a1[0], a1[1], a1[2], a1[3], b1[0], b1[2]);
        MMAH(acc[1][3][0], acc[1][3][1], acc[1][3][2], acc[1][3][3], a1[0], a1[1], a1[2], a1[3], b1[1], b1[3]);
    }

    __half* G = (mat == 0) ? g_qh : (mat == 1) ? g_kh : g_vh;
#pragma unroll
    for (int rg = 0; rg < 2; rg++) {
#pragma unroll
        for (int ng = 0; ng < 4; ng++) {
            int co = obase + wc + ng * 8 + 2 * cq;   // 0..127 within matrix
            int h = co >> 5, d = co & 31;
            int prow0 = rowbase + wr + rg * 16 + r;
            int b = prow0 >> 12, pp = prow0 & 4095;
            size_t base0 = ((size_t)((b * HH + h)) * SS + pp) * DH + d;
            u32 pk0; CVTH2(pk0, acc[rg][ng][1], acc[rg][ng][0]);
            *(u32*)(G + base0) = pk0;
            u32 pk1; CVTH2(pk1, acc[rg][ng][3], acc[rg][ng][2]);
            *(u32*)(G + base0 + (size_t)8 * DH) = pk1;
        }
    }
}

// ---------------- 3) attention: R8 + ones-MMA l + hoisted addresses -------
// grid (BHT, SS/128, KS), 128 threads (4 warps x 32 queries)
__global__ void __launch_bounds__(128, 5) attn_kernel()
{
    int bh = blockIdx.x;
    int qt = blockIdx.y;
    int ks = blockIdx.z;
    int tid = threadIdx.x;
    int w = tid >> 5, lane = tid & 31;
    int lrow = lane & 15, lchunk = lane >> 4;

    __shared__ __align__(16) __half sK[2 * 64 * 32];
    __shared__ __align__(16) __half sV[2 * 64 * 32];

    // hoisted per-thread staging offsets (elements)
    int stg0 = swoff(tid >> 2, tid & 3);
    int stg1 = swoff((tid + 128) >> 2, (tid + 128) & 3);
    u32 cK0 = smaddr(sK + stg0), cK1 = smaddr(sK + stg1);
    u32 cV0 = smaddr(sV + stg0), cV1 = smaddr(sV + stg1);

    // ---- stage Q tile (128 rows = both halves of sK) ----
    // rows 64..127 live at +2048 halfs; swizzle XOR invariant under row+64
    {
        const uint4* gQ = (const uint4*)(g_qh + ((size_t)bh * SS + qt * 128) * DH);
        *(uint4*)(sK + stg0) = gQ[tid];
        *(uint4*)(sK + stg1) = gQ[tid + 128];
        *(uint4*)(sK + stg0 + 2048) = gQ[tid + 256];
        *(uint4*)(sK + stg1 + 2048) = gQ[tid + 384];
    }
    __syncthreads();
    u32 qf0[8], qf1[8];
    {
        int row0 = w * 32 + lrow;
        LDSM4(qf0[0], qf0[1], qf0[2], qf0[3], smaddr(sK + swoff(row0, lchunk)));
        LDSM4(qf0[4], qf0[5], qf0[6], qf0[7], smaddr(sK + swoff(row0, 2 + lchunk)));
        int row1 = row0 + 16;
        LDSM4(qf1[0], qf1[1], qf1[2], qf1[3], smaddr(sK + swoff(row1, lchunk)));
        LDSM4(qf1[4], qf1[5], qf1[6], qf1[7], smaddr(sK + swoff(row1, 2 + lchunk)));
    }
    __syncthreads();   // done reading Q before cp.async overwrites sK

    // hoisted LDSM base addresses (kt stride = 1024B, buffer stride = 4096B;
    // swizzle XOR is kt-invariant: ((kt*16+lrow)>>1)&3 == (lrow>>1)&3)
    u32 aK0 = smaddr(sK + swoff(lrow, lchunk));
    u32 aK1 = smaddr(sK + swoff(lrow, 2 + lchunk));
    u32 aV0 = smaddr(sV + swoff(lrow, lchunk));
    u32 aV1 = smaddr(sV + swoff(lrow, 2 + lchunk));

    u32 oA[8], oB[8];
#pragma unroll
    for (int i = 0; i < 8; i++) { oA[i] = 0u; oB[i] = 0u; }
    u32 laA0 = 0u, laA1 = 0u, laB0 = 0u, laB1 = 0u;   // l accumulators (f16x2)

    const int kbase = ks * (SS / KS);               // 1024 keys per split
    const __half* gK = g_kh + ((size_t)bh * SS + kbase) * DH;
    const __half* gV = g_vh + ((size_t)bh * SS + kbase) * DH;
    const int NCH = SS / KS / 64;                   // 16 chunks of 64 keys

    // prefetch chunk 0
    {
        const uint4* srcK = (const uint4*)gK;
        const uint4* srcV = (const uint4*)gV;
        CPASYNC16(cK0, srcK + tid);
        CPASYNC16(cK1, srcK + tid + 128);
        CPASYNC16(cV0, srcV + tid);
        CPASYNC16(cV1, srcV + tid + 128);
        CPCOMMIT();
    }

    for (int ch = 0; ch < NCH; ch++) {
        u32 bufb = (ch & 1) * 4096;                 // byte offset of active buf
        if (ch + 1 < NCH) {
            const uint4* srcK = (const uint4*)(gK + (size_t)(ch + 1) * 64 * DH);
            const uint4* srcV = (const uint4*)(gV + (size_t)(ch + 1) * 64 * DH);
            u32 nb = ((ch + 1) & 1) * 4096;
            CPASYNC16(cK0 + nb, srcK + tid);
            CPASYNC16(cK1 + nb, srcK + tid + 128);
            CPASYNC16(cV0 + nb, srcV + tid);
            CPASYNC16(cV1 + nb, srcV + tid + 128);
            CPCOMMIT();
            CPWAIT(1);
        } else {
            CPWAIT(0);
        }
        __syncthreads();

#pragma unroll
        for (int kt = 0; kt < 4; kt++) {            // 16 keys per step
            u32 kb = bufb + kt * 1024;
            u32 k0[4], k1[4], v0[4], v1[4];
            LDSM4 (k0[0], k0[1], k0[2], k0[3], aK0 + kb);
            LDSM4 (k1[0], k1[1], k1[2], k1[3], aK1 + kb);
            LDSM4T(v0[0], v0[1], v0[2], v0[3], aV0 + kb);
            LDSM4T(v1[0], v1[1], v1[2], v1[3], aV1 + kb);

            // ---- group A (queries w*32 .. +15) ----
            u32 aA0 = 0u, aA1 = 0u, aB0 = 0u, aB1 = 0u;
            MMAH16(aA0, aA1, qf0[0], qf0[1], qf0[2], qf0[3], k0[0], k0[2]);
            MMAH16(aA0, aA1, qf0[4], qf0[5], qf0[6], qf0[7], k1[0], k1[2]);
            MMAH16(aB0, aB1, qf0[0], qf0[1], qf0[2], qf0[3], k0[1], k0[3]);
            MMAH16(aB0, aB1, qf0[4], qf0[5], qf0[6], qf0[7], k1[1], k1[3]);
            EX2H2(aA0, aA0); EX2H2(aA1, aA1); EX2H2(aB0, aB0); EX2H2(aB1, aB1);
            MMAH16(laA0, laA1, aA0, aA1, aB0, aB1, ONESH2, ONESH2);   // l += P.1
            MMAH16(oA[0], oA[1], aA0, aA1, aB0, aB1, v0[0], v0[1]);
            MMAH16(oA[2], oA[3], aA0, aA1, aB0, aB1, v0[2], v0[3]);
            MMAH16(oA[4], oA[5], aA0, aA1, aB0, aB1, v1[0], v1[1]);
            MMAH16(oA[6], oA[7], aA0, aA1, aB0, aB1, v1[2], v1[3]);

            // ---- group B (queries w*32+16 .. +31) ----
            u32 bA0 = 0u, bA1 = 0u, bB0 = 0u, bB1 = 0u;
            MMAH16(bA0, bA1, qf1[0], qf1[1], qf1[2], qf1[3], k0[0], k0[2]);
            MMAH16(bA0, bA1, qf1[4], qf1[5], qf1[6], qf1[7], k1[0], k1[2]);
            MMAH16(bB0, bB1, qf1[0], qf1[1], qf1[2], qf1[3], k0[1], k0[3]);
            MMAH16(bB0, bB1, qf1[4], qf1[5], qf1[6], qf1[7], k1[1], k1[3]);
            EX2H2(bA0, bA0); EX2H2(bA1, bA1); EX2H2(bB0, bB0); EX2H2(bB1, bB1);
            MMAH16(laB0, laB1, bA0, bA1, bB0, bB1, ONESH2, ONESH2);   // l += P.1
            MMAH16(oB[0], oB[1], bA0, bA1, bB0, bB1, v0[0], v0[1]);
            MMAH16(oB[2], oB[3], bA0, bA1, bB0, bB1, v0[2], v0[3]);
            MMAH16(oB[4], oB[5], bA0, bA1, bB0, bB1, v1[0], v1[1]);
            MMAH16(oB[6], oB[7], bA0, bA1, bB0, bB1, v1[2], v1[3]);
        }
        __syncthreads();
    }

    // extract l (every lane holds its row's full sum; all D columns equal)
    float lA0, lA1, lB0, lB1, dumm;
    H2TOF2(lA0, dumm, laA0);
    H2TOF2(lA1, dumm, laA1);
    H2TOF2(lB0, dumm, laB0);
    H2TOF2(lB1, dumm, laB1);

    int r = lane >> 2, cq = lane & 3;
    int qgA = qt * 128 + w * 32 + r;
    int qgB = qgA + 16;
    if (cq == 0) {
        g_lpart[((size_t)bh * SS + qgA) * KS + ks]     = lA0;
        g_lpart[((size_t)bh * SS + qgA + 8) * KS + ks] = lA1;
        g_lpart[((size_t)bh * SS + qgB) * KS + ks]     = lB0;
        g_lpart[((size_t)bh * SS + qgB + 8) * KS + ks] = lB1;
    }
#pragma unroll
    for (int d = 0; d < 4; d++) {
        *(u32*)(g_oparth + (((size_t)bh * SS + qgA)     * KS + ks) * DH + d * 8 + cq * 2) = oA[d * 2 + 0];
        *(u32*)(g_oparth + (((size_t)bh * SS + qgA + 8) * KS + ks) * DH + d * 8 + cq * 2) = oA[d * 2 + 1];
        *(u32*)(g_oparth + (((size_t)bh * SS + qgB)     * KS + ks) * DH + d * 8 + cq * 2) = oB[d * 2 + 0];
        *(u32*)(g_oparth + (((size_t)bh * SS + qgB + 8) * KS + ks) * DH + d * 8 + cq * 2) = oB[d * 2 + 1];
    }
}

// ---------------- 4) fused combine + output projection (scalar, R8) -------
__global__ void __launch_bounds__(128) outfused_kernel(
    const float* __restrict__ Wo, float* __restrict__ out)
{
    const int R = 16;
    __shared__ __align__(16) float zs[R][DD];
    __shared__ float ls[R][HH];
    int rowbase = blockIdx.x * R;
    int tid = threadIdx.x;

    // phase A: per-(row, head) inverse-l
    if (tid < R * HH) {
        int rr = tid >> 2, h = tid & 3;
        int grow = rowbase + rr;
        int b = grow >> 12, p = grow & 4095;
        int bh = b * HH + h;
        float l = 0.f;
#pragma unroll
        for (int k = 0; k < KS; k++) l += g_lpart[((size_t)bh * SS + p) * KS + k];
        ls[rr][h] = 0.5f / l;
    }
    __syncthreads();

    // phase B: build z tile
#pragma unroll
    for (int rr4 = 0; rr4 < 4; rr4++) {
        int e = rr4 * 128 + tid;          // 0..511 : 4-wide d chunk
        int row = e >> 5, fq = e & 31;
        int h = fq >> 3, dq = fq & 7;
        int grow = rowbase + row;
        int b = grow >> 12, p = grow & 4095;
        int bh = b * HH + h;
        float ox = 0.f, oy = 0.f, oz = 0.f, ow = 0.f;
#pragma unroll
        for (int k = 0; k < KS; k++) {
            uint2 t = ((const uint2*)(g_oparth + (((size_t)bh * SS + p) * KS + k) * DH))[dq];
            float2 lo = __half22float2(*(const __half2*)&t.x);
            float2 hi = __half22float2(*(const __half2*)&t.y);
            ox += lo.x; oy += lo.y; oz += hi.x; ow += hi.y;
        }
        float inv = ls[row][h];
        float4 vs = ((const float4*)(g_vsum + bh * DH))[dq];
        float4 z;
        z.x = fmaf(ox, inv, 0.5f * vs.x);
        z.y = fmaf(oy, inv, 0.5f * vs.y);
        z.z = fmaf(oz, inv, 0.5f * vs.z);
        z.w = fmaf(ow, inv, 0.5f * vs.w);
        *(float4*)(&zs[row][fq * 4]) = z;
    }
    __syncthreads();

    // phase C: out = z @ Wo^T
    const float4* Wr = (const float4*)(Wo + tid * DD);
    float acc[R];
#pragma unroll
    for (int r = 0; r < R; r++) acc[r] = 0.f;
#pragma unroll 8
    for (int jc = 0; jc < DD / 4; jc++) {
        float4 w = Wr[jc];
#pragma unroll
        for (int r = 0; r < R; r++) {
            float4 zv = *(const float4*)(&zs[r][jc * 4]);
            acc[r] = fmaf(w.x, zv.x, acc[r]);
            acc[r] = fmaf(w.y, zv.y, acc[r]);
            acc[r] = fmaf(w.z, zv.z, acc[r]);
            acc[r] = fmaf(w.w, zv.w, acc[r]);
        }
    }
#pragma unroll
    for (int r = 0; r < R; r++)
        out[(size_t)(rowbase + r) * DD + tid] = acc[r];
}

// ---------------- launch ----------------
extern "C" void kernel_launch(void* const* d_in, const int* in_sizes, int n_in,
                              void* d_out, int out_size)
{
    const float* x  = (const float*)d_in[0];
    const float* Wk = (const float*)d_in[1];
    const float* Wq = (const float*)d_in[2];
    const float* Wv = (const float*)d_in[3];
    const float* Wo = (const float*)d_in[4];
    float* out = (float*)d_out;

    prep_kernel<<<256, 256>>>(x, Wk, Wq, Wv);
    vsumw_kernel<<<BHT, 128>>>(Wv);
    projmma_kernel<<<dim3(6, (BB * SS) / 64), 128>>>();
    {
        dim3 grid(BHT, SS / 128, KS);
        attn_kernel<<<grid, 128>>>();
    }
    outfused_kernel<<<(BB * SS) / 16, 128>>>(Wo, out);
}